// round 2
// baseline (speedup 1.0000x reference)
#include <cuda_runtime.h>
#include <cstdint>

#define BATCH     64
#define HH        1024
#define WW        1024
#define OUTN      256
#define ROWS_PER_BLOCK 32
#define BLOCKS_PER_BATCH (HH / ROWS_PER_BLOCK)   // 32
#define QUADS_PER_ROW (WW / 4)                   // 256

// Per-block partial statistics, written unconditionally every launch -> no init
// kernel needed. Layout: [BATCH][BLOCKS_PER_BATCH][7]
// 7 stats: count, sumr, sumc, minr, maxr, minc, maxc
__device__ int g_part[BATCH][BLOCKS_PER_BATCH][7];

// Per-batch arrival tickets. Zero-initialized at module load; the finishing
// block resets its counter to 0 each launch, so every graph replay starts
// from the same state (deterministic).
__device__ unsigned int g_ticket[BATCH];

__global__ __launch_bounds__(256) void gss_fused_kernel(const float4* __restrict__ mask,
                                                        const float* __restrict__ Wm,
                                                        const float* __restrict__ bias,
                                                        float* __restrict__ out) {
    const int blk   = blockIdx.x;
    const int batch = blk / BLOCKS_PER_BATCH;
    const int bslot = blk % BLOCKS_PER_BATCH;
    const int row0  = bslot * ROWS_PER_BLOCK;
    const int t     = threadIdx.x;            // 0..255, one float4 column-quad per thread
    const int col0  = t * 4;

    const float4* base = mask
        + (size_t)batch * (HH * QUADS_PER_ROW)
        + (size_t)row0 * QUADS_PER_ROW
        + t;

    int count = 0, sumr = 0, sumc = 0;
    int minr = HH, maxr = -1, minc = WW, maxc = -1;

    #pragma unroll 8
    for (int r = 0; r < ROWS_PER_BLOCK; ++r) {
        float4 v = __ldcs(base + (size_t)r * QUADS_PER_ROW);  // streaming: no reuse
        int i0 = (v.x != 0.0f);
        int i1 = (v.y != 0.0f);
        int i2 = (v.z != 0.0f);
        int i3 = (v.w != 0.0f);
        int rc = i0 + i1 + i2 + i3;
        if (rc) {
            int row = row0 + r;
            count += rc;
            sumr  += row * rc;
            sumc  += col0 * rc + i1 + 2 * i2 + 3 * i3;
            minr = min(minr, row);
            maxr = row;  // rows ascend within the loop
            unsigned m = (unsigned)(i0 | (i1 << 1) | (i2 << 2) | (i3 << 3));
            minc = min(minc, col0 + (__ffs(m) - 1));
            maxc = max(maxc, col0 + (31 - __clz(m)));
        }
    }

    // ---- intra-block reduction ----
    const unsigned full = 0xFFFFFFFFu;
    #pragma unroll
    for (int off = 16; off > 0; off >>= 1) {
        count += __shfl_down_sync(full, count, off);
        sumr  += __shfl_down_sync(full, sumr,  off);
        sumc  += __shfl_down_sync(full, sumc,  off);
        minr  = min(minr, __shfl_down_sync(full, minr, off));
        maxr  = max(maxr, __shfl_down_sync(full, maxr, off));
        minc  = min(minc, __shfl_down_sync(full, minc, off));
        maxc  = max(maxc, __shfl_down_sync(full, maxc, off));
    }

    __shared__ int s_cnt[8], s_sr[8], s_sc[8], s_mnr[8], s_mxr[8], s_mnc[8], s_mxc[8];
    __shared__ int s_is_last;
    __shared__ float s_feat[6];
    int wid = t >> 5, lid = t & 31;
    if (lid == 0) {
        s_cnt[wid] = count; s_sr[wid] = sumr; s_sc[wid] = sumc;
        s_mnr[wid] = minr;  s_mxr[wid] = maxr;
        s_mnc[wid] = minc;  s_mxc[wid] = maxc;
    }
    __syncthreads();

    if (t < 8) {
        count = s_cnt[t]; sumr = s_sr[t]; sumc = s_sc[t];
        minr = s_mnr[t]; maxr = s_mxr[t];
        minc = s_mnc[t]; maxc = s_mxc[t];
        #pragma unroll
        for (int off = 4; off > 0; off >>= 1) {
            count += __shfl_down_sync(0xFF, count, off);
            sumr  += __shfl_down_sync(0xFF, sumr,  off);
            sumc  += __shfl_down_sync(0xFF, sumc,  off);
            minr  = min(minr, __shfl_down_sync(0xFF, minr, off));
            maxr  = max(maxr, __shfl_down_sync(0xFF, maxr, off));
            minc  = min(minc, __shfl_down_sync(0xFF, minc, off));
            maxc  = max(maxc, __shfl_down_sync(0xFF, maxc, off));
        }
        if (t == 0) {
            int* p = g_part[batch][bslot];
            p[0] = count; p[1] = sumr; p[2] = sumc;
            p[3] = minr;  p[4] = maxr;
            p[5] = minc;  p[6] = maxc;
            __threadfence();  // publish partials before taking a ticket
            unsigned old = atomicAdd(&g_ticket[batch], 1u);
            s_is_last = (old == BLOCKS_PER_BATCH - 1);
        }
    }
    __syncthreads();

    if (!s_is_last) return;

    // ---- last block of this batch: reduce partials + emit outputs ----
    if (t < 32) {
        __threadfence();  // acquire: make all blocks' partials visible
        const int* p = g_part[batch][t];
        count = p[0]; sumr = p[1]; sumc = p[2];
        minr = p[3]; maxr = p[4]; minc = p[5]; maxc = p[6];
        #pragma unroll
        for (int off = 16; off > 0; off >>= 1) {
            count += __shfl_down_sync(full, count, off);
            sumr  += __shfl_down_sync(full, sumr,  off);
            sumc  += __shfl_down_sync(full, sumc,  off);
            minr  = min(minr, __shfl_down_sync(full, minr, off));
            maxr  = max(maxr, __shfl_down_sync(full, maxr, off));
            minc  = min(minc, __shfl_down_sync(full, minc, off));
            maxc  = max(maxc, __shfl_down_sync(full, maxc, off));
        }
        if (t == 0) {
            float f0 = 0.f, f1 = 0.f, f2 = 0.f, f3 = 0.f, f4 = 0.f, f5 = 0.f;
            if (count > 0) {
                float fa = (float)count;
                float cr = (float)sumr / fa;
                float cc = (float)sumc / fa;
                float height = (float)(maxr - minr);
                float width  = (float)(maxc - minc);
                const float hw = (float)HH * (float)WW;
                f0 = cr / (float)HH;
                f1 = cc / (float)WW;
                f2 = height / (float)HH;
                f3 = width / (float)WW;
                f4 = fa / hw;
                f5 = height * width / hw;
            }
            s_feat[0] = f0; s_feat[1] = f1; s_feat[2] = f2;
            s_feat[3] = f3; s_feat[4] = f4; s_feat[5] = f5;
            g_ticket[batch] = 0;  // reset for the next graph replay
        }
    }
    __syncthreads();

    // 256 threads -> 256 output elements for this batch
    const float* wrow = Wm + t * 6;
    float acc = bias[t];
    acc = fmaf(s_feat[0], wrow[0], acc);
    acc = fmaf(s_feat[1], wrow[1], acc);
    acc = fmaf(s_feat[2], wrow[2], acc);
    acc = fmaf(s_feat[3], wrow[3], acc);
    acc = fmaf(s_feat[4], wrow[4], acc);
    acc = fmaf(s_feat[5], wrow[5], acc);
    out[batch * OUTN + t] = acc;
}

extern "C" void kernel_launch(void* const* d_in, const int* in_sizes, int n_in,
                              void* d_out, int out_size) {
    const float* mask = (const float*)d_in[0];   // (64,1,1024,1024) fp32
    const float* Wm   = (const float*)d_in[1];   // (256,6) fp32
    const float* bias = (const float*)d_in[2];   // (256,) fp32
    float* out = (float*)d_out;                  // (64,256) fp32

    gss_fused_kernel<<<BATCH * BLOCKS_PER_BATCH, 256>>>((const float4*)mask, Wm, bias, out);
}

// round 3
// speedup vs baseline: 1.0547x; 1.0547x over previous
#include <cuda_runtime.h>
#include <cstdint>

#define BATCH     64
#define HH        1024
#define WW        1024
#define OUTN      256
#define ROWS_PER_BLOCK 32
#define BLOCKS_PER_BATCH (HH / ROWS_PER_BLOCK)   // 32
#define QUADS_PER_ROW (WW / 4)                   // 256
#define GROUPS    4
#define ROWS_PER_GROUP 8                         // MLP batch

// Per-block partials, written unconditionally every launch (no init needed).
// [BATCH][BLOCKS_PER_BATCH][7]: count, sumr, sumc, minr, maxr, minc, maxc
__device__ int g_part[BATCH][BLOCKS_PER_BATCH][7];
// Per-batch arrival tickets; finishing block resets to 0 -> replay-deterministic.
__device__ unsigned int g_ticket[BATCH];

__global__ __launch_bounds__(256) void gss_fused_kernel(const float4* __restrict__ mask,
                                                        const float* __restrict__ Wm,
                                                        const float* __restrict__ bias,
                                                        float* __restrict__ out) {
    const int blk   = blockIdx.x;
    const int batch = blk / BLOCKS_PER_BATCH;
    const int bslot = blk % BLOCKS_PER_BATCH;
    const int row0  = bslot * ROWS_PER_BLOCK;
    const int t     = threadIdx.x;            // one float4 column-quad per thread
    const int col0  = t * 4;

    const float4* base = mask
        + (size_t)batch * (HH * QUADS_PER_ROW)
        + (size_t)row0 * QUADS_PER_ROW
        + t;

    // fp accumulators (exact: all integer-valued, per-thread max 131k < 2^24)
    float cnt_f = 0.0f;   // total hits
    float sr_f  = 0.0f;   // sum over rows of row * row_count
    float wc_f  = 0.0f;   // sum of (i1 + 2*i2 + 3*i3)
    // bbox accumulators
    unsigned c0 = 0, c1 = 0, c2 = 0, c3 = 0;  // per-column "ever nonzero"
    unsigned rm = 0;                           // per-row hit bitmap (32 rows)

    #pragma unroll
    for (int g = 0; g < GROUPS; ++g) {
        float4 v[ROWS_PER_GROUP];
        #pragma unroll
        for (int r = 0; r < ROWS_PER_GROUP; ++r)
            v[r] = __ldcs(base + (size_t)(g * ROWS_PER_GROUP + r) * QUADS_PER_ROW);

        #pragma unroll
        for (int r = 0; r < ROWS_PER_GROUP; ++r) {
            const int rr = g * ROWS_PER_GROUP + r;
            float t1 = v[r].x + v[r].y;
            float t2 = v[r].z + v[r].w;
            float rc = t1 + t2;                       // row hit count (0..4)
            cnt_f += rc;
            sr_f = fmaf((float)(row0 + rr), rc, sr_f);
            wc_f += v[r].y;
            wc_f = fmaf(v[r].z, 2.0f, wc_f);
            wc_f = fmaf(v[r].w, 3.0f, wc_f);
            c0 |= __float_as_uint(v[r].x);
            c1 |= __float_as_uint(v[r].y);
            c2 |= __float_as_uint(v[r].z);
            c3 |= __float_as_uint(v[r].w);
            if (rc != 0.0f) rm |= (1u << rr);         // FSETP + predicated OR-imm
        }
    }

    // ---- per-thread epilogue: recover bbox + exact int stats ----
    int count = (int)cnt_f;
    int sumr  = (int)sr_f;
    int sumc  = col0 * count + (int)wc_f;
    unsigned cb = (c0 ? 1u : 0u) | (c1 ? 2u : 0u) | (c2 ? 4u : 0u) | (c3 ? 8u : 0u);
    int minc = cb ? (col0 + (__ffs(cb) - 1)) : WW;
    int maxc = cb ? (col0 + (31 - __clz(cb))) : -1;
    int minr = rm ? (row0 + (__ffs(rm) - 1)) : HH;
    int maxr = rm ? (row0 + (31 - __clz(rm))) : -1;

    // ---- intra-block reduction ----
    const unsigned full = 0xFFFFFFFFu;
    #pragma unroll
    for (int off = 16; off > 0; off >>= 1) {
        count += __shfl_down_sync(full, count, off);
        sumr  += __shfl_down_sync(full, sumr,  off);
        sumc  += __shfl_down_sync(full, sumc,  off);
        minr  = min(minr, __shfl_down_sync(full, minr, off));
        maxr  = max(maxr, __shfl_down_sync(full, maxr, off));
        minc  = min(minc, __shfl_down_sync(full, minc, off));
        maxc  = max(maxc, __shfl_down_sync(full, maxc, off));
    }

    __shared__ int s_cnt[8], s_sr[8], s_sc[8], s_mnr[8], s_mxr[8], s_mnc[8], s_mxc[8];
    __shared__ int s_is_last;
    __shared__ float s_feat[6];
    int wid = t >> 5, lid = t & 31;
    if (lid == 0) {
        s_cnt[wid] = count; s_sr[wid] = sumr; s_sc[wid] = sumc;
        s_mnr[wid] = minr;  s_mxr[wid] = maxr;
        s_mnc[wid] = minc;  s_mxc[wid] = maxc;
    }
    __syncthreads();

    if (t < 8) {
        count = s_cnt[t]; sumr = s_sr[t]; sumc = s_sc[t];
        minr = s_mnr[t]; maxr = s_mxr[t];
        minc = s_mnc[t]; maxc = s_mxc[t];
        #pragma unroll
        for (int off = 4; off > 0; off >>= 1) {
            count += __shfl_down_sync(0xFF, count, off);
            sumr  += __shfl_down_sync(0xFF, sumr,  off);
            sumc  += __shfl_down_sync(0xFF, sumc,  off);
            minr  = min(minr, __shfl_down_sync(0xFF, minr, off));
            maxr  = max(maxr, __shfl_down_sync(0xFF, maxr, off));
            minc  = min(minc, __shfl_down_sync(0xFF, minc, off));
            maxc  = max(maxc, __shfl_down_sync(0xFF, maxc, off));
        }
        if (t == 0) {
            int* p = g_part[batch][bslot];
            p[0] = count; p[1] = sumr; p[2] = sumc;
            p[3] = minr;  p[4] = maxr;
            p[5] = minc;  p[6] = maxc;
            __threadfence();
            unsigned old = atomicAdd(&g_ticket[batch], 1u);
            s_is_last = (old == BLOCKS_PER_BATCH - 1);
        }
    }
    __syncthreads();

    if (!s_is_last) return;

    // ---- last block of this batch: reduce partials + emit outputs ----
    if (t < 32) {
        __threadfence();
        const int* p = g_part[batch][t];
        count = p[0]; sumr = p[1]; sumc = p[2];
        minr = p[3]; maxr = p[4]; minc = p[5]; maxc = p[6];
        #pragma unroll
        for (int off = 16; off > 0; off >>= 1) {
            count += __shfl_down_sync(full, count, off);
            sumr  += __shfl_down_sync(full, sumr,  off);
            sumc  += __shfl_down_sync(full, sumc,  off);
            minr  = min(minr, __shfl_down_sync(full, minr, off));
            maxr  = max(maxr, __shfl_down_sync(full, maxr, off));
            minc  = min(minc, __shfl_down_sync(full, minc, off));
            maxc  = max(maxc, __shfl_down_sync(full, maxc, off));
        }
        if (t == 0) {
            float f0 = 0.f, f1 = 0.f, f2 = 0.f, f3 = 0.f, f4 = 0.f, f5 = 0.f;
            if (count > 0) {
                float fa = (float)count;
                float cr = (float)sumr / fa;
                float cc = (float)sumc / fa;
                float height = (float)(maxr - minr);
                float width  = (float)(maxc - minc);
                const float hw = (float)HH * (float)WW;
                f0 = cr / (float)HH;
                f1 = cc / (float)WW;
                f2 = height / (float)HH;
                f3 = width / (float)WW;
                f4 = fa / hw;
                f5 = height * width / hw;
            }
            s_feat[0] = f0; s_feat[1] = f1; s_feat[2] = f2;
            s_feat[3] = f3; s_feat[4] = f4; s_feat[5] = f5;
            g_ticket[batch] = 0;  // reset for next graph replay
        }
    }
    __syncthreads();

    const float* wrow = Wm + t * 6;
    float acc = bias[t];
    acc = fmaf(s_feat[0], wrow[0], acc);
    acc = fmaf(s_feat[1], wrow[1], acc);
    acc = fmaf(s_feat[2], wrow[2], acc);
    acc = fmaf(s_feat[3], wrow[3], acc);
    acc = fmaf(s_feat[4], wrow[4], acc);
    acc = fmaf(s_feat[5], wrow[5], acc);
    out[batch * OUTN + t] = acc;
}

extern "C" void kernel_launch(void* const* d_in, const int* in_sizes, int n_in,
                              void* d_out, int out_size) {
    const float* mask = (const float*)d_in[0];   // (64,1,1024,1024) fp32
    const float* Wm   = (const float*)d_in[1];   // (256,6) fp32
    const float* bias = (const float*)d_in[2];   // (256,) fp32
    float* out = (float*)d_out;                  // (64,256) fp32

    gss_fused_kernel<<<BATCH * BLOCKS_PER_BATCH, 256>>>((const float4*)mask, Wm, bias, out);
}

// round 4
// speedup vs baseline: 1.0953x; 1.0385x over previous
#include <cuda_runtime.h>
#include <cstdint>

#define BATCH     64
#define HH        1024
#define WW        1024
#define OUTN      256
#define ROWS_PER_BLOCK 8
#define BLOCKS_PER_BATCH (HH / ROWS_PER_BLOCK)   // 128
#define QUADS_PER_ROW (WW / 4)                   // 256

// Per-block partials, written unconditionally every launch (no init needed).
// [BATCH][BLOCKS_PER_BATCH][7]: count, sumr, sumc, minr, maxr, minc, maxc
__device__ int g_part[BATCH][BLOCKS_PER_BATCH][7];
// Per-batch arrival tickets; finishing block resets to 0 -> replay-deterministic.
__device__ unsigned int g_ticket[BATCH];

__global__ __launch_bounds__(256) void gss_fused_kernel(const float4* __restrict__ mask,
                                                        const float* __restrict__ Wm,
                                                        const float* __restrict__ bias,
                                                        float* __restrict__ out) {
    const int blk   = blockIdx.x;
    const int batch = blk / BLOCKS_PER_BATCH;
    const int bslot = blk % BLOCKS_PER_BATCH;
    const int row0  = bslot * ROWS_PER_BLOCK;
    const int t     = threadIdx.x;            // one float4 column-quad per thread
    const int col0  = t * 4;

    const float4* base = mask
        + (size_t)batch * (HH * QUADS_PER_ROW)
        + (size_t)row0 * QUADS_PER_ROW
        + t;

    // Front-batched loads: 8 outstanding LDG.128 per thread
    float4 v[ROWS_PER_BLOCK];
    #pragma unroll
    for (int r = 0; r < ROWS_PER_BLOCK; ++r)
        v[r] = __ldcs(base + (size_t)r * QUADS_PER_ROW);

    // fp accumulators (exact: all integer-valued, small)
    float cnt_f = 0.0f;   // total hits
    float sr_f  = 0.0f;   // sum of row * row_count
    float wc_f  = 0.0f;   // sum of (i1 + 2*i2 + 3*i3)
    unsigned c0 = 0, c1 = 0, c2 = 0, c3 = 0;  // per-column "ever nonzero"
    unsigned rm = 0;                           // per-row hit bitmap (8 rows)

    #pragma unroll
    for (int r = 0; r < ROWS_PER_BLOCK; ++r) {
        float t1 = v[r].x + v[r].y;
        float t2 = v[r].z + v[r].w;
        float rc = t1 + t2;                   // row hit count (0..4)
        cnt_f += rc;
        sr_f = fmaf((float)(row0 + r), rc, sr_f);
        wc_f += v[r].y;
        wc_f = fmaf(v[r].z, 2.0f, wc_f);
        wc_f = fmaf(v[r].w, 3.0f, wc_f);
        c0 |= __float_as_uint(v[r].x);
        c1 |= __float_as_uint(v[r].y);
        c2 |= __float_as_uint(v[r].z);
        c3 |= __float_as_uint(v[r].w);
        if (rc != 0.0f) rm |= (1u << r);      // FSETP + predicated OR-imm
    }

    // ---- per-thread epilogue: recover bbox + exact int stats ----
    int count = (int)cnt_f;
    int sumr  = (int)sr_f;
    int sumc  = col0 * count + (int)wc_f;
    unsigned cb = (c0 ? 1u : 0u) | (c1 ? 2u : 0u) | (c2 ? 4u : 0u) | (c3 ? 8u : 0u);
    int minc = cb ? (col0 + (__ffs(cb) - 1)) : WW;
    int maxc = cb ? (col0 + (31 - __clz(cb))) : -1;
    int minr = rm ? (row0 + (__ffs(rm) - 1)) : HH;
    int maxr = rm ? (row0 + (31 - __clz(rm))) : -1;

    // ---- intra-block reduction ----
    const unsigned full = 0xFFFFFFFFu;
    #pragma unroll
    for (int off = 16; off > 0; off >>= 1) {
        count += __shfl_down_sync(full, count, off);
        sumr  += __shfl_down_sync(full, sumr,  off);
        sumc  += __shfl_down_sync(full, sumc,  off);
        minr  = min(minr, __shfl_down_sync(full, minr, off));
        maxr  = max(maxr, __shfl_down_sync(full, maxr, off));
        minc  = min(minc, __shfl_down_sync(full, minc, off));
        maxc  = max(maxc, __shfl_down_sync(full, maxc, off));
    }

    __shared__ int s_cnt[8], s_sr[8], s_sc[8], s_mnr[8], s_mxr[8], s_mnc[8], s_mxc[8];
    __shared__ int s_is_last;
    __shared__ float s_feat[6];
    int wid = t >> 5, lid = t & 31;
    if (lid == 0) {
        s_cnt[wid] = count; s_sr[wid] = sumr; s_sc[wid] = sumc;
        s_mnr[wid] = minr;  s_mxr[wid] = maxr;
        s_mnc[wid] = minc;  s_mxc[wid] = maxc;
    }
    __syncthreads();

    if (t < 8) {
        count = s_cnt[t]; sumr = s_sr[t]; sumc = s_sc[t];
        minr = s_mnr[t]; maxr = s_mxr[t];
        minc = s_mnc[t]; maxc = s_mxc[t];
        #pragma unroll
        for (int off = 4; off > 0; off >>= 1) {
            count += __shfl_down_sync(0xFF, count, off);
            sumr  += __shfl_down_sync(0xFF, sumr,  off);
            sumc  += __shfl_down_sync(0xFF, sumc,  off);
            minr  = min(minr, __shfl_down_sync(0xFF, minr, off));
            maxr  = max(maxr, __shfl_down_sync(0xFF, maxr, off));
            minc  = min(minc, __shfl_down_sync(0xFF, minc, off));
            maxc  = max(maxc, __shfl_down_sync(0xFF, maxc, off));
        }
        if (t == 0) {
            int* p = g_part[batch][bslot];
            p[0] = count; p[1] = sumr; p[2] = sumc;
            p[3] = minr;  p[4] = maxr;
            p[5] = minc;  p[6] = maxc;
            __threadfence();
            unsigned old = atomicAdd(&g_ticket[batch], 1u);
            s_is_last = (old == BLOCKS_PER_BATCH - 1);
        }
    }
    __syncthreads();

    if (!s_is_last) return;

    // ---- last block of this batch: reduce 128 partials + emit outputs ----
    {
        __threadfence();  // acquire: make all blocks' partials visible
        if (t < 128) {
            const int* p = g_part[batch][t];
            count = p[0]; sumr = p[1]; sumc = p[2];
            minr = p[3]; maxr = p[4]; minc = p[5]; maxc = p[6];
        } else {
            count = 0; sumr = 0; sumc = 0;
            minr = HH; maxr = -1; minc = WW; maxc = -1;
        }
        #pragma unroll
        for (int off = 16; off > 0; off >>= 1) {
            count += __shfl_down_sync(full, count, off);
            sumr  += __shfl_down_sync(full, sumr,  off);
            sumc  += __shfl_down_sync(full, sumc,  off);
            minr  = min(minr, __shfl_down_sync(full, minr, off));
            maxr  = max(maxr, __shfl_down_sync(full, maxr, off));
            minc  = min(minc, __shfl_down_sync(full, minc, off));
            maxc  = max(maxc, __shfl_down_sync(full, maxc, off));
        }
        if (lid == 0 && wid < 4) {
            s_cnt[wid] = count; s_sr[wid] = sumr; s_sc[wid] = sumc;
            s_mnr[wid] = minr;  s_mxr[wid] = maxr;
            s_mnc[wid] = minc;  s_mxc[wid] = maxc;
        }
    }
    __syncthreads();

    if (t == 0) {
        count = s_cnt[0] + s_cnt[1] + s_cnt[2] + s_cnt[3];
        sumr  = s_sr[0]  + s_sr[1]  + s_sr[2]  + s_sr[3];
        sumc  = s_sc[0]  + s_sc[1]  + s_sc[2]  + s_sc[3];
        minr  = min(min(s_mnr[0], s_mnr[1]), min(s_mnr[2], s_mnr[3]));
        maxr  = max(max(s_mxr[0], s_mxr[1]), max(s_mxr[2], s_mxr[3]));
        minc  = min(min(s_mnc[0], s_mnc[1]), min(s_mnc[2], s_mnc[3]));
        maxc  = max(max(s_mxc[0], s_mxc[1]), max(s_mxc[2], s_mxc[3]));

        float f0 = 0.f, f1 = 0.f, f2 = 0.f, f3 = 0.f, f4 = 0.f, f5 = 0.f;
        if (count > 0) {
            float fa = (float)count;
            float cr = (float)sumr / fa;
            float cc = (float)sumc / fa;
            float height = (float)(maxr - minr);
            float width  = (float)(maxc - minc);
            const float hw = (float)HH * (float)WW;
            f0 = cr / (float)HH;
            f1 = cc / (float)WW;
            f2 = height / (float)HH;
            f3 = width / (float)WW;
            f4 = fa / hw;
            f5 = height * width / hw;
        }
        s_feat[0] = f0; s_feat[1] = f1; s_feat[2] = f2;
        s_feat[3] = f3; s_feat[4] = f4; s_feat[5] = f5;
        g_ticket[batch] = 0;  // reset for next graph replay
    }
    __syncthreads();

    // 256 threads -> 256 output elements for this batch
    const float* wrow = Wm + t * 6;
    float acc = bias[t];
    acc = fmaf(s_feat[0], wrow[0], acc);
    acc = fmaf(s_feat[1], wrow[1], acc);
    acc = fmaf(s_feat[2], wrow[2], acc);
    acc = fmaf(s_feat[3], wrow[3], acc);
    acc = fmaf(s_feat[4], wrow[4], acc);
    acc = fmaf(s_feat[5], wrow[5], acc);
    out[batch * OUTN + t] = acc;
}

extern "C" void kernel_launch(void* const* d_in, const int* in_sizes, int n_in,
                              void* d_out, int out_size) {
    const float* mask = (const float*)d_in[0];   // (64,1,1024,1024) fp32
    const float* Wm   = (const float*)d_in[1];   // (256,6) fp32
    const float* bias = (const float*)d_in[2];   // (256,) fp32
    float* out = (float*)d_out;                  // (64,256) fp32

    gss_fused_kernel<<<BATCH * BLOCKS_PER_BATCH, 256>>>((const float4*)mask, Wm, bias, out);
}